// round 16
// baseline (speedup 1.0000x reference)
#include <cuda_runtime.h>
#include <cuda_fp16.h>
#include <cstdint>

#define T_TOK    16384
#define DIM      2048
#define NEXP     64
#define NB       4
#define SEQ      4096
#define BM       32              // tokens per CTA
#define BK       64              // k per chunk (4 x k16 blocks)
#define NCHUNK   (DIM / BK)      // 32
#define NTHREADS 256
#define GRID     (T_TOK / BM)    // 512
#define NKB      (DIM / 16)      // 128 k16-blocks

#define WSCALE   1024.0f
#define XSCALE   256.0f
#define UNSCALE  (1.0f / (WSCALE * XSCALE))   // 2^-18 exact

// smem: W stages 3 x 16384 B (chunk = 4 kb x 64 e x 4 tg x 16B = 16 KB)
#define WSTAGE_B 16384
#define NSTAGE   3
#define SMEM_BYTES (NSTAGE * WSTAGE_B)        // 49152
// epilogue reuse: red[4][32][68] f32 = 34816 B <= 49152

__device__ uint4    g_wfrag[NKB * NEXP * 4];  // 512 KB, [kb][e][tg]
__device__ float    g_score_sum[NB * NEXP];
__device__ unsigned g_counts[NB * NEXP];
__device__ unsigned g_done;

__device__ __forceinline__ void split_pair(float x0, float x1,
                                           uint32_t& p1, uint32_t& p2) {
    __half2 h1 = __floats2half2_rn(x0, x1);
    float2  f  = __half22float2(h1);
    __half2 h2 = __floats2half2_rn(x0 - f.x, x1 - f.y);
    p1 = *reinterpret_cast<uint32_t*>(&h1);
    p2 = *reinterpret_cast<uint32_t*>(&h2);
}

__device__ __forceinline__ void mma_f16(float* c,
                                        uint32_t a0, uint32_t a1, uint32_t a2, uint32_t a3,
                                        uint32_t b0, uint32_t b1) {
    asm volatile(
        "mma.sync.aligned.m16n8k16.row.col.f32.f16.f16.f32 "
        "{%0,%1,%2,%3}, {%4,%5,%6,%7}, {%8,%9}, {%0,%1,%2,%3};"
        : "+f"(c[0]), "+f"(c[1]), "+f"(c[2]), "+f"(c[3])
        : "r"(a0), "r"(a1), "r"(a2), "r"(a3), "r"(b0), "r"(b1));
}

__device__ __forceinline__ uint32_t smem_u32(const void* p) {
    uint32_t a;
    asm("{ .reg .u64 t; cvta.to.shared.u64 t, %1; cvt.u32.u64 %0, t; }" : "=r"(a) : "l"(p));
    return a;
}

#define CP_ASYNC16(dst_u32, src_ptr) \
    asm volatile("cp.async.cg.shared.global [%0], [%1], 16;" :: "r"(dst_u32), "l"(src_ptr) : "memory")
#define CP_COMMIT()  asm volatile("cp.async.commit_group;" ::: "memory")
#define CP_WAIT1()   asm volatile("cp.async.wait_group 1;" ::: "memory")
#define CP_WAIT0()   asm volatile("cp.async.wait_group 0;" ::: "memory")

__global__ void presplit_w_kernel(const float* __restrict__ W) {
    int idx = blockIdx.x * 256 + threadIdx.x;     // 0..32767
    int tg = idx & 3;
    int e  = (idx >> 2) & 63;
    int kb = idx >> 8;
    const float* src = W + (size_t)e * DIM + kb * 16;
    float2 lo = *(const float2*)(src + 2 * tg);
    float2 hi = *(const float2*)(src + 2 * tg + 8);
    uint32_t w0, w1, w2, w3;
    split_pair(lo.x * WSCALE, lo.y * WSCALE, w0, w2);
    split_pair(hi.x * WSCALE, hi.y * WSCALE, w1, w3);
    g_wfrag[idx] = make_uint4(w0, w1, w2, w3);
}

__device__ __forceinline__ void issue_w_chunk(uint32_t smem_base, int stage,
                                              int kt, int tid) {
    const uint32_t d = smem_base + stage * WSTAGE_B + tid * 16;
    const uint4* s = &g_wfrag[kt * 1024 + tid];
    CP_ASYNC16(d,                 s);
    CP_ASYNC16(d + 256 * 16, s + 256);
    CP_ASYNC16(d + 512 * 16, s + 512);
    CP_ASYNC16(d + 768 * 16, s + 768);
    CP_COMMIT();
}

__global__ __launch_bounds__(NTHREADS, 3)
void moe_gate_f16(const float* __restrict__ X,
                  float* __restrict__ out)
{
    extern __shared__ char smem[];
    __shared__ unsigned int cnt[NEXP];
    __shared__ int last_flag;

    const int tid  = threadIdx.x;
    const int wid  = tid >> 5;
    const int lane = tid & 31;
    const int g    = lane >> 2;       // 0..7
    const int tg   = lane & 3;        // 0..3
    const int tgp  = wid >> 2;        // token group 0..1 (16 tokens each)
    const int ksl  = wid & 3;         // k16-slice within k64 chunk
    const int tok0 = blockIdx.x * BM;
    const int row0 = tgp * 16 + g;

    const uint32_t smem_base = smem_u32(smem);
    const int boff = ksl * 4096 + g * 64 + tg * 16;  // consumer byte offset in stage

    const float* Xr0 = X + (size_t)(tok0 + row0) * DIM + ksl * 16 + 2 * tg;
    const float* Xr1 = Xr0 + 8 * DIM;

    float acc[8][4];
#pragma unroll
    for (int nt = 0; nt < 8; nt++)
#pragma unroll
        for (int i = 0; i < 4; i++) acc[nt][i] = 0.0f;

    // ---- prolog: W chunks 0,1 via cp.async; X chunk 0 via LDG ----
    issue_w_chunk(smem_base, 0, 0, tid);
    issue_w_chunk(smem_base, 1, 1, tid);
    float2 ra0 = *(const float2*)(Xr0);
    float2 ra2 = *(const float2*)(Xr0 + 8);
    float2 ra1 = *(const float2*)(Xr1);
    float2 ra3 = *(const float2*)(Xr1 + 8);
    if (tid < NEXP) cnt[tid] = 0u;
    CP_WAIT1();            // chunk 0 resident
    __syncthreads();

    for (int kt = 0; kt < NCHUNK; kt++) {
        const int stage = kt % NSTAGE;

        // issue W for chunk kt+2 into stage (kt+2)%3 (consumed 2 iters ago)
        if (kt + 2 < NCHUNK)
            issue_w_chunk(smem_base, (kt + 2) % NSTAGE, kt + 2, tid);

        // split current (scaled) A
        uint32_t ah1[4], ah2[4];
        split_pair(ra0.x * XSCALE, ra0.y * XSCALE, ah1[0], ah2[0]);
        split_pair(ra1.x * XSCALE, ra1.y * XSCALE, ah1[1], ah2[1]);
        split_pair(ra2.x * XSCALE, ra2.y * XSCALE, ah1[2], ah2[2]);
        split_pair(ra3.x * XSCALE, ra3.y * XSCALE, ah1[3], ah2[3]);

        // prefetch next X (overlaps MMA)
        if (kt + 1 < NCHUNK) {
            const float* xn0 = Xr0 + (kt + 1) * BK;
            const float* xn1 = Xr1 + (kt + 1) * BK;
            ra0 = *(const float2*)(xn0);
            ra2 = *(const float2*)(xn0 + 8);
            ra1 = *(const float2*)(xn1);
            ra3 = *(const float2*)(xn1 + 8);
        }

        // compute: 8 n-tiles x 4 MMAs on this k16 slice
        const char* Bbase = smem + stage * WSTAGE_B;
#pragma unroll
        for (int nt = 0; nt < 8; nt++) {
            uint4 b = *(const uint4*)(Bbase + boff + nt * 512);
            mma_f16(acc[nt], ah1[0], ah1[1], ah1[2], ah1[3], b.x, b.y);  // h1*h1
            mma_f16(acc[nt], ah1[0], ah1[1], ah1[2], ah1[3], b.z, b.w);  // h1*h2
            mma_f16(acc[nt], ah2[0], ah2[1], ah2[2], ah2[3], b.x, b.y);  // h2*h1
            mma_f16(acc[nt], ah2[0], ah2[1], ah2[2], ah2[3], b.z, b.w);  // h2*h2
        }

        // next chunk must be resident before anyone computes it
        if (kt + 2 < NCHUNK) { CP_WAIT1(); } else { CP_WAIT0(); }
        __syncthreads();
    }

    // ---- epilogue: red[4][32][68] (k16-slice partials), unscale 2^-18 ----
    float* red = (float*)smem;
#pragma unroll
    for (int nt = 0; nt < 8; nt++) {
        const int e = nt * 8 + 2 * tg;
        *(float2*)&red[(ksl * 32 + row0) * 68 + e] =
            make_float2(acc[nt][0] * UNSCALE, acc[nt][1] * UNSCALE);
        *(float2*)&red[(ksl * 32 + row0 + 8) * 68 + e] =
            make_float2(acc[nt][2] * UNSCALE, acc[nt][3] * UNSCALE);
    }
    __syncthreads();

    // reduce 4 k-slices into rows 0-31
    for (int i = tid; i < BM * NEXP; i += NTHREADS) {
        const int t = i >> 6, e = i & 63;
        red[t * 68 + e] = red[t * 68 + e]
                        + red[(32 + t) * 68 + e]
                        + red[(64 + t) * 68 + e]
                        + red[(96 + t) * 68 + e];
    }
    __syncthreads();

    float* sc = red;   // [32][68]

    // ---- per-token softmax + top-2 (smem-resident, spill-free) ----
    if (tid < BM) {
        float* row = &sc[tid * 68];
        float mx = row[0];
#pragma unroll
        for (int e = 1; e < NEXP; e++) mx = fmaxf(mx, row[e]);
        float sum = 0.0f;
#pragma unroll
        for (int e = 0; e < NEXP; e++) { float p = expf(row[e] - mx); row[e] = p; sum += p; }
        float inv = 1.0f / sum;

        float v1 = -1.0f, v2 = -1.0f;
        int i1 = 0, i2 = 0;
#pragma unroll
        for (int e = 0; e < NEXP; e++) {
            float p = row[e] * inv;
            row[e] = p;
            if (p > v1) { v2 = v1; i2 = i1; v1 = p; i1 = e; }
            else if (p > v2) { v2 = p; i2 = e; }
        }
        float tot = v1 + v2 + 1e-20f;
        const int gt = tok0 + tid;
        out[2 * gt + 0] = (float)i1;
        out[2 * gt + 1] = (float)i2;
        out[2 * T_TOK + 2 * gt + 0] = v1 / tot;
        out[2 * T_TOK + 2 * gt + 1] = v2 / tot;

        atomicAdd(&cnt[i1], 1u);
        atomicAdd(&cnt[i2], 1u);
    }
    __syncthreads();

    // ---- per-expert sums -> global ----
    if (tid < NEXP) {
        float cs = 0.0f;
#pragma unroll 8
        for (int t = 0; t < BM; t++) cs += sc[t * 68 + tid];
        const int b = tok0 / SEQ;
        atomicAdd(&g_score_sum[b * NEXP + tid], cs);
        atomicAdd(&g_counts[b * NEXP + tid], cnt[tid]);
    }

    // ---- last-block finalize (aux loss) ----
    __threadfence();
    __syncthreads();
    if (tid == 0) {
        unsigned int v = atomicAdd(&g_done, 1u);
        last_flag = (v == (unsigned int)(GRID - 1));
    }
    __syncthreads();
    if (last_flag) {
        float* redf = (float*)smem;
        const int i = tid;            // 256 = NB*NEXP
        float sv = *((volatile float*)&g_score_sum[i]);
        unsigned int cv = *((volatile unsigned int*)&g_counts[i]);
        float v = (float)cv * ((float)NEXP / (float)(SEQ * 2)) * (sv / (float)SEQ);
        g_score_sum[i] = 0.0f;
        g_counts[i] = 0u;
        if (tid == 0) g_done = 0u;
        redf[i] = v;
        __syncthreads();
        for (int s = (NB * NEXP) / 2; s > 0; s >>= 1) {
            if (i < s) redf[i] += redf[i + s];
            __syncthreads();
        }
        if (i == 0) out[4 * T_TOK] = redf[0] * (0.1f / (float)NB);
    }
}

extern "C" void kernel_launch(void* const* d_in, const int* in_sizes, int n_in,
                              void* d_out, int out_size) {
    const float* X = (const float*)d_in[0];   // [4,4096,2048] f32
    const float* W = (const float*)d_in[1];   // [64,2048] f32
    float* out = (float*)d_out;

    presplit_w_kernel<<<NKB * NEXP * 4 / 256, 256>>>(W);
    cudaFuncSetAttribute(moe_gate_f16, cudaFuncAttributeMaxDynamicSharedMemorySize, SMEM_BYTES);
    moe_gate_f16<<<GRID, NTHREADS, SMEM_BYTES>>>(X, out);
}